// round 4
// baseline (speedup 1.0000x reference)
#include <cuda_runtime.h>
#include <cstdint>

// ---------------- problem constants ----------------
#define N_ATOMS   500000
#define N_PER_DEG 125000
#define NODE      128
#define EDGE      64
#define OUT_C     128
#define TILE_M    128
#define N_TILES   977          // ceil(125000/128)
#define BN_EPS    1e-5f

// ---------------- SMEM layout (dynamic) ----------------
// [0, 1024):      s_sum[128], s_sq[128]
// [1024, 166912): Wsm uint32[128][324]      (W as tf32, [n][k], stride 324)
// [166912, ...):  Aring uint32[3][128][36]  (summed A chunks, tf32)
#define W_STRIDE  324
#define A_STRIDE  36
#define OFF_STATS 0
#define OFF_W     1024
#define OFF_A     166912
#define A_BUFSZ   (128 * A_STRIDE)            // words per stage
#define N_STAGES  3
#define SMEM_TOTAL (OFF_A + N_STAGES * A_BUFSZ * 4)   // 222208

#define BAR_SYNC_512(id)   asm volatile("bar.sync %0, 512;"   :: "r"(id) : "memory")
#define BAR_ARRIVE_512(id) asm volatile("bar.arrive %0, 512;" :: "r"(id) : "memory")
#define BAR_SYNC_256(id)   asm volatile("bar.sync %0, 256;"   :: "r"(id) : "memory")

__device__ __forceinline__ uint32_t f2tf32(float f) {
    uint32_t r;
    asm("cvt.rna.tf32.f32 %0, %1;" : "=r"(r) : "f"(f));
    return r;
}

__device__ __forceinline__ void mma_m16n8k8(float d[4], const uint32_t a[4],
                                            uint32_t b0, uint32_t b1) {
    asm volatile(
        "mma.sync.aligned.m16n8k8.row.col.f32.tf32.tf32.f32 "
        "{%0,%1,%2,%3}, {%4,%5,%6,%7}, {%8,%9}, {%0,%1,%2,%3};"
        : "+f"(d[0]), "+f"(d[1]), "+f"(d[2]), "+f"(d[3])
        : "r"(a[0]), "r"(a[1]), "r"(a[2]), "r"(a[3]), "r"(b0), "r"(b1));
}

// ---------------- BN scratch ----------------
__device__ float g_sum[OUT_C];
__device__ float g_sumsq[OUT_C];
__device__ float g_mean[OUT_C];
__device__ float g_istd[OUT_C];

// ---------------- fused gather + tf32 GEMM + bias + stats body ----------------
// 512 threads = 16 warps: warps 0-7 consumers (MMA), warps 8-15 producers (gather).
// K = 320 in 10 chunks of 32 cols:
//   0-3: atom-neighbor sum; 4-5: bond-neighbor sum; 6-9: self row.
template <int DEG>
__device__ __forceinline__
void gconv_body(const float* __restrict__ atom_repr,
                const float* __restrict__ bond_repr,
                const int*   __restrict__ aidx,
                const int*   __restrict__ bidx,
                const float* __restrict__ Wd,
                const float* __restrict__ Wself,
                const float* __restrict__ bias,
                float*       __restrict__ out,
                int deg_base, int tile_base, char* smem) {
    float*    s_sum = (float*)(smem + OFF_STATS);
    float*    s_sq  = s_sum + OUT_C;
    uint32_t* Wsm   = (uint32_t*)(smem + OFF_W);
    uint32_t* Aring = (uint32_t*)(smem + OFF_A);

    const int tid  = threadIdx.x;
    const int wid  = tid >> 5;
    const int lane = tid & 31;

    if (tid < OUT_C) { s_sum[tid] = 0.f; s_sq[tid] = 0.f; }

    // ---- cooperative W = [Wd | Wself] load -> tf32 smem, layout Wsm[n][k] ----
    for (int e4 = tid; e4 < OUT_C * 80; e4 += 512) {
        int n  = e4 / 80;
        int k4 = (e4 - n * 80) * 4;
        const float* src = (k4 < 192) ? (Wd + n * 192 + k4) : (Wself + n * 128 + (k4 - 192));
        float4 v = __ldg((const float4*)src);
        *(uint4*)(Wsm + n * W_STRIDE + k4) =
            make_uint4(f2tf32(v.x), f2tf32(v.y), f2tf32(v.z), f2tf32(v.w));
    }
    __syncthreads();

    if (wid >= 8) {
        // ================= PRODUCER =================
        const int ptid = tid - 256;
        const int r = ptid >> 1;          // row 0..127
        const int h = ptid & 1;           // 16-col half of 32-col chunk
        const int row_in_deg = tile_base + r;
        const bool gvalid = row_in_deg < N_PER_DEG;
        const int rid = gvalid ? row_in_deg : (N_PER_DEG - 1);

        int ai[DEG], bi[DEG];
#pragma unroll
        for (int j = 0; j < DEG; j++) {
            ai[j] = aidx[rid * DEG + j];
            bi[j] = bidx[rid * DEG + j];
        }
        const int selfrow = deg_base + rid;

        float4 vr[DEG][4];

        auto load_chunk = [&](int c) {
            if (c < 4) {
                int co = c * 32 + h * 16;
#pragma unroll
                for (int j = 0; j < DEG; j++) {
                    const float4* p = (const float4*)(atom_repr + (size_t)ai[j] * NODE + co);
#pragma unroll
                    for (int i = 0; i < 4; i++) vr[j][i] = __ldg(p + i);
                }
            } else if (c < 6) {
                int co = (c - 4) * 32 + h * 16;
#pragma unroll
                for (int j = 0; j < DEG; j++) {
                    const float4* p = (const float4*)(bond_repr + (size_t)bi[j] * EDGE + co);
#pragma unroll
                    for (int i = 0; i < 4; i++) vr[j][i] = __ldg(p + i);
                }
            } else {
                int co = (c - 6) * 32 + h * 16;
                const float4* p = (const float4*)(atom_repr + (size_t)selfrow * NODE + co);
#pragma unroll
                for (int i = 0; i < 4; i++) vr[0][i] = __ldg(p + i);
            }
        };

        auto store_chunk = [&](int c, uint32_t* stage) {
            float4 s[4];
#pragma unroll
            for (int i = 0; i < 4; i++) s[i] = vr[0][i];
            if (c < 6) {
#pragma unroll
                for (int j = 1; j < DEG; j++)
#pragma unroll
                    for (int i = 0; i < 4; i++) {
                        s[i].x += vr[j][i].x; s[i].y += vr[j][i].y;
                        s[i].z += vr[j][i].z; s[i].w += vr[j][i].w;
                    }
            }
            if (!gvalid) {
#pragma unroll
                for (int i = 0; i < 4; i++) s[i] = make_float4(0.f, 0.f, 0.f, 0.f);
            }
            uint32_t* dst = stage + r * A_STRIDE + h * 16;
#pragma unroll
            for (int i = 0; i < 4; i++)
                *(uint4*)(dst + i * 4) =
                    make_uint4(f2tf32(s[i].x), f2tf32(s[i].y), f2tf32(s[i].z), f2tf32(s[i].w));
        };

        load_chunk(0);
        int s = 0;
#pragma unroll
        for (int c = 0; c < 10; c++) {
            if (c >= N_STAGES) BAR_SYNC_512(4 + s);      // wait stage freed
            store_chunk(c, Aring + s * A_BUFSZ);
            BAR_ARRIVE_512(1 + s);                        // publish stage full
            if (c < 9) load_chunk(c + 1);                 // overlap next gather
            s = (s == N_STAGES - 1) ? 0 : s + 1;
        }
    } else {
        // ================= CONSUMER =================
        const int warp_m = wid & 3;
        const int warp_n = wid >> 2;      // 0..1, 64 N-cols each

        float acc[2][8][4];
#pragma unroll
        for (int mi = 0; mi < 2; mi++)
#pragma unroll
            for (int nb = 0; nb < 8; nb++)
#pragma unroll
                for (int i = 0; i < 4; i++) acc[mi][nb][i] = 0.f;

        int s = 0;
#pragma unroll
        for (int c = 0; c < 10; c++) {
            BAR_SYNC_512(1 + s);                          // wait stage full
            const uint32_t* buf = Aring + s * A_BUFSZ;
#pragma unroll
            for (int st = 0; st < 4; st++) {
                const int kk = st * 8 + (lane & 3);
                uint32_t a[2][4];
#pragma unroll
                for (int mi = 0; mi < 2; mi++) {
                    int row = warp_m * 32 + mi * 16 + (lane >> 2);
                    a[mi][0] = buf[row * A_STRIDE + kk];
                    a[mi][1] = buf[(row + 8) * A_STRIDE + kk];
                    a[mi][2] = buf[row * A_STRIDE + kk + 4];
                    a[mi][3] = buf[(row + 8) * A_STRIDE + kk + 4];
                }
                const int kb = c * 32 + kk;
#pragma unroll
                for (int nb = 0; nb < 8; nb++) {
                    int n = warp_n * 64 + nb * 8 + (lane >> 2);
                    uint32_t b0 = Wsm[n * W_STRIDE + kb];
                    uint32_t b1 = Wsm[n * W_STRIDE + kb + 4];
                    mma_m16n8k8(acc[0][nb], a[0], b0, b1);
                    mma_m16n8k8(acc[1][nb], a[1], b0, b1);
                }
            }
            BAR_ARRIVE_512(4 + s);                        // release stage
            s = (s == N_STAGES - 1) ? 0 : s + 1;
        }

        // ---- epilogue: bias + store + fused BN partial stats ----
#pragma unroll
        for (int nb = 0; nb < 8; nb++) {
            const int col0 = warp_n * 64 + nb * 8 + (lane & 3) * 2;
            const float bv0 = __ldg(bias + col0);
            const float bv1 = __ldg(bias + col0 + 1);
            float ps0 = 0.f, ps1 = 0.f, pq0 = 0.f, pq1 = 0.f;
#pragma unroll
            for (int mi = 0; mi < 2; mi++) {
                int gr0 = tile_base + warp_m * 32 + mi * 16 + (lane >> 2);
                float x00 = acc[mi][nb][0] + bv0;
                float x01 = acc[mi][nb][1] + bv1;
                float x10 = acc[mi][nb][2] + bv0;
                float x11 = acc[mi][nb][3] + bv1;
                if (gr0 < N_PER_DEG) {
                    *(float2*)(out + (size_t)(deg_base + gr0) * OUT_C + col0) = make_float2(x00, x01);
                    ps0 += x00; ps1 += x01; pq0 += x00 * x00; pq1 += x01 * x01;
                }
                if (gr0 + 8 < N_PER_DEG) {
                    *(float2*)(out + (size_t)(deg_base + gr0 + 8) * OUT_C + col0) = make_float2(x10, x11);
                    ps0 += x10; ps1 += x11; pq0 += x10 * x10; pq1 += x11 * x11;
                }
            }
#pragma unroll
            for (int m = 4; m < 32; m <<= 1) {
                ps0 += __shfl_xor_sync(0xffffffffu, ps0, m);
                ps1 += __shfl_xor_sync(0xffffffffu, ps1, m);
                pq0 += __shfl_xor_sync(0xffffffffu, pq0, m);
                pq1 += __shfl_xor_sync(0xffffffffu, pq1, m);
            }
            if ((lane >> 2) == 0) {
                atomicAdd(&s_sum[col0], ps0);
                atomicAdd(&s_sum[col0 + 1], ps1);
                atomicAdd(&s_sq[col0], pq0);
                atomicAdd(&s_sq[col0 + 1], pq1);
            }
        }

        BAR_SYNC_256(7);                                  // consumers only
        if (tid < OUT_C) {
            atomicAdd(&g_sum[tid], s_sum[tid]);
            atomicAdd(&g_sumsq[tid], s_sq[tid]);
        }
    }
}

// ---------------- merged kernel: all 4 degrees in one launch ----------------
__global__ __launch_bounds__(512, 1)
void gconv_all(const float* __restrict__ atom_repr,
               const float* __restrict__ bond_repr,
               const int* __restrict__ a1, const int* __restrict__ a2,
               const int* __restrict__ a3, const int* __restrict__ a4,
               const int* __restrict__ b1, const int* __restrict__ b2,
               const int* __restrict__ b3, const int* __restrict__ b4,
               const float* __restrict__ W1, const float* __restrict__ W2,
               const float* __restrict__ W3, const float* __restrict__ W4,
               const float* __restrict__ Wself,
               const float* __restrict__ bias,
               float* __restrict__ out) {
    extern __shared__ char smem[];
    const int d = blockIdx.x & 3;
    const int tile_base = (blockIdx.x >> 2) * TILE_M;
    switch (d) {
        case 0: gconv_body<1>(atom_repr, bond_repr, a1, b1, W1, Wself, bias, out, 0 * N_PER_DEG, tile_base, smem); break;
        case 1: gconv_body<2>(atom_repr, bond_repr, a2, b2, W2, Wself, bias, out, 1 * N_PER_DEG, tile_base, smem); break;
        case 2: gconv_body<3>(atom_repr, bond_repr, a3, b3, W3, Wself, bias, out, 2 * N_PER_DEG, tile_base, smem); break;
        default: gconv_body<4>(atom_repr, bond_repr, a4, b4, W4, Wself, bias, out, 3 * N_PER_DEG, tile_base, smem); break;
    }
}

// ---------------- aux kernels ----------------
__global__ void zero_stats_kernel() {
    if (threadIdx.x < OUT_C) { g_sum[threadIdx.x] = 0.f; g_sumsq[threadIdx.x] = 0.f; }
}

__global__ void finalize_stats_kernel() {
    int c = threadIdx.x;
    if (c < OUT_C) {
        float mean = g_sum[c] * (1.0f / N_ATOMS);
        float var = g_sumsq[c] * (1.0f / N_ATOMS) - mean * mean;
        g_mean[c] = mean;
        g_istd[c] = rsqrtf(var + BN_EPS);
    }
}

__global__ void bn_relu_kernel(float4* __restrict__ x, int n4) {
    int t = blockIdx.x * blockDim.x + threadIdx.x;
    int stride = gridDim.x * blockDim.x;   // multiple of 32
    int c = (t & 31) * 4;
    float m0 = g_mean[c + 0], m1 = g_mean[c + 1], m2 = g_mean[c + 2], m3 = g_mean[c + 3];
    float i0 = g_istd[c + 0], i1 = g_istd[c + 1], i2 = g_istd[c + 2], i3 = g_istd[c + 3];
    for (int i = t; i < n4; i += stride) {
        float4 v = x[i];
        v.x = fmaxf((v.x - m0) * i0, 0.f);
        v.y = fmaxf((v.y - m1) * i1, 0.f);
        v.z = fmaxf((v.z - m2) * i2, 0.f);
        v.w = fmaxf((v.w - m3) * i3, 0.f);
        x[i] = v;
    }
}

// ---------------- launch ----------------
extern "C" void kernel_launch(void* const* d_in, const int* in_sizes, int n_in,
                              void* d_out, int out_size) {
    (void)n_in; (void)out_size;

    const float* atom_repr = (const float*)d_in[0];
    const float* bond_repr = (const float*)d_in[1];
    const int* aidx[4];
    const int* bidx[4];
    const float* W[4];

    if (in_sizes[4] == OUT_C * (NODE + EDGE)) {
        for (int d = 0; d < 4; d++) {
            aidx[d] = (const int*)d_in[2 + 3 * d];
            bidx[d] = (const int*)d_in[3 + 3 * d];
            W[d]    = (const float*)d_in[4 + 3 * d];
        }
    } else {
        for (int d = 0; d < 4; d++) {
            aidx[d] = (const int*)d_in[2 + d];
            bidx[d] = (const int*)d_in[6 + d];
            W[d]    = (const float*)d_in[10 + d];
        }
    }
    const float* Wself = (const float*)d_in[14];
    const float* bias  = (const float*)d_in[15];
    float* out = (float*)d_out;

    cudaFuncSetAttribute(gconv_all, cudaFuncAttributeMaxDynamicSharedMemorySize, SMEM_TOTAL);

    zero_stats_kernel<<<1, 128>>>();
    gconv_all<<<4 * N_TILES, 512, SMEM_TOTAL>>>(
        atom_repr, bond_repr,
        aidx[0], aidx[1], aidx[2], aidx[3],
        bidx[0], bidx[1], bidx[2], bidx[3],
        W[0], W[1], W[2], W[3],
        Wself, bias, out);

    finalize_stats_kernel<<<1, 128>>>();
    const int n4 = (N_ATOMS * OUT_C) / 4;
    bn_relu_kernel<<<2960, 256>>>((float4*)out, n4);
}

// round 5
// speedup vs baseline: 1.5844x; 1.5844x over previous
#include <cuda_runtime.h>
#include <cstdint>

// ---------------- problem constants ----------------
#define N_ATOMS   500000
#define N_PER_DEG 125000
#define NODE      128
#define EDGE      64
#define OUT_C     128
#define ASUM_C    192
#define TILE_M    128
#define N_TILES   977          // ceil(125000/128)
#define BN_EPS    1e-5f

__device__ __forceinline__ uint32_t f2tf32(float f) {
    uint32_t r;
    asm("cvt.rna.tf32.f32 %0, %1;" : "=r"(r) : "f"(f));
    return r;
}
__device__ __forceinline__ float f2tf32f(float f) {
    return __uint_as_float(f2tf32(f));
}

__device__ __forceinline__ void mma_m16n8k8(float d[4], const uint32_t a[4],
                                            uint32_t b0, uint32_t b1) {
    asm volatile(
        "mma.sync.aligned.m16n8k8.row.col.f32.tf32.tf32.f32 "
        "{%0,%1,%2,%3}, {%4,%5,%6,%7}, {%8,%9}, {%0,%1,%2,%3};"
        : "+f"(d[0]), "+f"(d[1]), "+f"(d[2]), "+f"(d[3])
        : "r"(a[0]), "r"(a[1]), "r"(a[2]), "r"(a[3]), "r"(b0), "r"(b1));
}

// cp.async helpers
__device__ __forceinline__ uint32_t smem_u32(const void* p) {
    uint32_t a;
    asm("{ .reg .u64 t; cvta.to.shared.u64 t, %1; cvt.u32.u64 %0, t; }" : "=r"(a) : "l"(p));
    return a;
}
#define CP_ASYNC16(dst, src) \
    asm volatile("cp.async.cg.shared.global [%0], [%1], 16;" :: "r"(dst), "l"(src) : "memory")
#define CP_COMMIT() asm volatile("cp.async.commit_group;" ::: "memory")
#define CP_WAIT1()  asm volatile("cp.async.wait_group 1;" ::: "memory")
#define CP_WAIT0()  asm volatile("cp.async.wait_group 0;" ::: "memory")

// ---------------- device scratch (allocation-free) ----------------
__device__ float g_Asum[(size_t)N_ATOMS * ASUM_C];     // 384 MB gathered+summed features (tf32-rounded)
__device__ float g_Wtf[4][OUT_C * 192];                // per-degree W, tf32-rounded
__device__ float g_Wselftf[OUT_C * NODE];              // W_self, tf32-rounded
__device__ float g_sum[OUT_C];
__device__ float g_sumsq[OUT_C];
__device__ float g_mean[OUT_C];
__device__ float g_istd[OUT_C];

// ---------------- K0: zero stats + convert W to tf32 ----------------
__global__ void zero_stats_kernel() {
    if (threadIdx.x < OUT_C) { g_sum[threadIdx.x] = 0.f; g_sumsq[threadIdx.x] = 0.f; }
}

__global__ void wconv_kernel(const float* __restrict__ W1, const float* __restrict__ W2,
                             const float* __restrict__ W3, const float* __restrict__ W4,
                             const float* __restrict__ Wself) {
    int t = blockIdx.x * blockDim.x + threadIdx.x;
    const int nWd = OUT_C * 192;
    if (t < nWd) {
        g_Wtf[0][t] = f2tf32f(__ldg(W1 + t));
        g_Wtf[1][t] = f2tf32f(__ldg(W2 + t));
        g_Wtf[2][t] = f2tf32f(__ldg(W3 + t));
        g_Wtf[3][t] = f2tf32f(__ldg(W4 + t));
    }
    if (t < OUT_C * NODE) g_Wselftf[t] = f2tf32f(__ldg(Wself + t));
}

// ---------------- Phase 1: gather + sum -> g_Asum ----------------
template <int DEG>
__device__ __forceinline__
void gather_row(const float* __restrict__ atom_repr, const float* __restrict__ bond_repr,
                const int* __restrict__ ap, const int* __restrict__ bp,
                int rid, float* __restrict__ dst, int lane) {
    int ai[DEG], bi[DEG];
#pragma unroll
    for (int j = 0; j < DEG; j++) ai[j] = __ldg(ap + rid * DEG + j);
#pragma unroll
    for (int j = 0; j < DEG; j++) bi[j] = __ldg(bp + rid * DEG + j);

    float4 va[DEG];
    float2 vb[DEG];
#pragma unroll
    for (int j = 0; j < DEG; j++)
        va[j] = __ldg((const float4*)(atom_repr + (size_t)ai[j] * NODE) + lane);
#pragma unroll
    for (int j = 0; j < DEG; j++)
        vb[j] = __ldg((const float2*)(bond_repr + (size_t)bi[j] * EDGE) + lane);

    float4 s = va[0];
    float2 t = vb[0];
#pragma unroll
    for (int j = 1; j < DEG; j++) {
        s.x += va[j].x; s.y += va[j].y; s.z += va[j].z; s.w += va[j].w;
        t.x += vb[j].x; t.y += vb[j].y;
    }
    float4 so = make_float4(f2tf32f(s.x), f2tf32f(s.y), f2tf32f(s.z), f2tf32f(s.w));
    float2 to = make_float2(f2tf32f(t.x), f2tf32f(t.y));
    ((float4*)dst)[lane] = so;
    ((float2*)(dst + NODE))[lane] = to;
}

__global__ __launch_bounds__(256)
void gather_kernel(const float* __restrict__ atom_repr, const float* __restrict__ bond_repr,
                   const int* __restrict__ a1, const int* __restrict__ a2,
                   const int* __restrict__ a3, const int* __restrict__ a4,
                   const int* __restrict__ b1, const int* __restrict__ b2,
                   const int* __restrict__ b3, const int* __restrict__ b4) {
    const int w = (blockIdx.x * 256 + threadIdx.x) >> 5;   // one warp per row
    if (w >= N_ATOMS) return;
    const int lane = threadIdx.x & 31;
    const int deg = w / N_PER_DEG;
    const int rid = w - deg * N_PER_DEG;
    float* dst = g_Asum + (size_t)w * ASUM_C;
    switch (deg) {
        case 0:  gather_row<1>(atom_repr, bond_repr, a1, b1, rid, dst, lane); break;
        case 1:  gather_row<2>(atom_repr, bond_repr, a2, b2, rid, dst, lane); break;
        case 2:  gather_row<3>(atom_repr, bond_repr, a3, b3, rid, dst, lane); break;
        default: gather_row<4>(atom_repr, bond_repr, a4, b4, rid, dst, lane); break;
    }
}

// ---------------- Phase 2: pipelined GEMM + bias + BN stats ----------------
// 256 threads, 8 warps; warp tile 32(M) x 64(N). K=320 in 10 chunks of 32:
//   chunks 0-5 from g_Asum, chunks 6-9 from atom_repr (contiguous self rows).
// 3-stage cp.async pipeline; stage = A[128][36] + W[128][36] (words).
#define P2_STRIDE 36
#define P2_STAGE_WORDS (128 * P2_STRIDE)
#define P2_OFF_STATS (3 * P2_STAGE_WORDS * 2 * 4)      // after 3 stages (A+W each)
#define P2_SMEM (P2_OFF_STATS + 1024)                  // 221184 + 1024 -> wait, recompute

// stage s: A at s*2*P2_STAGE_WORDS, W at s*2*P2_STAGE_WORDS + P2_STAGE_WORDS
// 3 stages * 2 * 4608 words * 4B = 110592 B; + 1KB stats = 111616 B
#undef P2_OFF_STATS
#undef P2_SMEM
#define P2_OFF_STATS 110592
#define P2_SMEM      111616

__global__ __launch_bounds__(256, 2)
void gemm_kernel(const float* __restrict__ atom_repr,
                 const float* __restrict__ bias,
                 float* __restrict__ out) {
    extern __shared__ char smem[];
    uint32_t* sbase = (uint32_t*)smem;
    float* s_sum = (float*)(smem + P2_OFF_STATS);
    float* s_sq  = s_sum + OUT_C;

    const int tid  = threadIdx.x;
    const int wid  = tid >> 5;
    const int lane = tid & 31;
    const int warp_m = wid & 3;
    const int warp_n = wid >> 2;

    const int d = blockIdx.x & 3;
    const int tile_base = (blockIdx.x >> 2) * TILE_M;
    const int deg_base = d * N_PER_DEG;
    const float* __restrict__ Wd = g_Wtf[d];

    if (tid < OUT_C) { s_sum[tid] = 0.f; s_sq[tid] = 0.f; }

    const uint32_t smem_addr = smem_u32(smem);

    auto issue_stage = [&](int c, int s) {
        const uint32_t aoff = smem_addr + (uint32_t)(s * 2 * P2_STAGE_WORDS) * 4;
        const uint32_t woff = aoff + (uint32_t)P2_STAGE_WORDS * 4;
#pragma unroll
        for (int i = 0; i < 4; i++) {
            int idx = tid + i * 256;
            int row = idx >> 3;
            int q   = idx & 7;
            int rg  = tile_base + row;
            if (rg >= N_PER_DEG) rg = N_PER_DEG - 1;
            const float* asrc = (c < 6)
                ? g_Asum + (size_t)(deg_base + rg) * ASUM_C + c * 32 + q * 4
                : atom_repr + (size_t)(deg_base + rg) * NODE + (c - 6) * 32 + q * 4;
            CP_ASYNC16(aoff + (uint32_t)(row * P2_STRIDE + q * 4) * 4, asrc);
            const float* wsrc = (c < 6)
                ? Wd + row * 192 + c * 32 + q * 4
                : g_Wselftf + row * NODE + (c - 6) * 32 + q * 4;
            CP_ASYNC16(woff + (uint32_t)(row * P2_STRIDE + q * 4) * 4, wsrc);
        }
        CP_COMMIT();
    };

    float acc[2][8][4];
#pragma unroll
    for (int mi = 0; mi < 2; mi++)
#pragma unroll
        for (int nb = 0; nb < 8; nb++)
#pragma unroll
            for (int i = 0; i < 4; i++) acc[mi][nb][i] = 0.f;

    issue_stage(0, 0);
    issue_stage(1, 1);

    int s = 0;
#pragma unroll
    for (int c = 0; c < 10; c++) {
        CP_WAIT1();
        __syncthreads();
        if (c + 2 < 10) issue_stage(c + 2, (c + 2 == 2) ? 2 : ((c + 2) % 3));

        const uint32_t* As = sbase + s * 2 * P2_STAGE_WORDS;
        const uint32_t* Ws = As + P2_STAGE_WORDS;
#pragma unroll
        for (int st = 0; st < 4; st++) {
            const int kk = st * 8 + (lane & 3);
            uint32_t a[2][4];
#pragma unroll
            for (int mi = 0; mi < 2; mi++) {
                int row = warp_m * 32 + mi * 16 + (lane >> 2);
                a[mi][0] = As[row * P2_STRIDE + kk];
                a[mi][1] = As[(row + 8) * P2_STRIDE + kk];
                a[mi][2] = As[row * P2_STRIDE + kk + 4];
                a[mi][3] = As[(row + 8) * P2_STRIDE + kk + 4];
            }
#pragma unroll
            for (int nb = 0; nb < 8; nb++) {
                int n = warp_n * 64 + nb * 8 + (lane >> 2);
                uint32_t b0 = Ws[n * P2_STRIDE + kk];
                uint32_t b1 = Ws[n * P2_STRIDE + kk + 4];
                mma_m16n8k8(acc[0][nb], a[0], b0, b1);
                mma_m16n8k8(acc[1][nb], a[1], b0, b1);
            }
        }
        s = (s == 2) ? 0 : s + 1;
    }

    // ---- epilogue: bias + store + fused BN partial stats ----
#pragma unroll
    for (int nb = 0; nb < 8; nb++) {
        const int col0 = warp_n * 64 + nb * 8 + (lane & 3) * 2;
        const float bv0 = __ldg(bias + col0);
        const float bv1 = __ldg(bias + col0 + 1);
        float ps0 = 0.f, ps1 = 0.f, pq0 = 0.f, pq1 = 0.f;
#pragma unroll
        for (int mi = 0; mi < 2; mi++) {
            int gr0 = tile_base + warp_m * 32 + mi * 16 + (lane >> 2);
            float x00 = acc[mi][nb][0] + bv0;
            float x01 = acc[mi][nb][1] + bv1;
            float x10 = acc[mi][nb][2] + bv0;
            float x11 = acc[mi][nb][3] + bv1;
            if (gr0 < N_PER_DEG) {
                *(float2*)(out + (size_t)(deg_base + gr0) * OUT_C + col0) = make_float2(x00, x01);
                ps0 += x00; ps1 += x01; pq0 += x00 * x00; pq1 += x01 * x01;
            }
            if (gr0 + 8 < N_PER_DEG) {
                *(float2*)(out + (size_t)(deg_base + gr0 + 8) * OUT_C + col0) = make_float2(x10, x11);
                ps0 += x10; ps1 += x11; pq0 += x10 * x10; pq1 += x11 * x11;
            }
        }
#pragma unroll
        for (int m = 4; m < 32; m <<= 1) {
            ps0 += __shfl_xor_sync(0xffffffffu, ps0, m);
            ps1 += __shfl_xor_sync(0xffffffffu, ps1, m);
            pq0 += __shfl_xor_sync(0xffffffffu, pq0, m);
            pq1 += __shfl_xor_sync(0xffffffffu, pq1, m);
        }
        if ((lane >> 2) == 0) {
            atomicAdd(&s_sum[col0], ps0);
            atomicAdd(&s_sum[col0 + 1], ps1);
            atomicAdd(&s_sq[col0], pq0);
            atomicAdd(&s_sq[col0 + 1], pq1);
        }
    }

    __syncthreads();
    if (tid < OUT_C) {
        atomicAdd(&g_sum[tid], s_sum[tid]);
        atomicAdd(&g_sumsq[tid], s_sq[tid]);
    }
}

// ---------------- finalize + BN/ReLU ----------------
__global__ void finalize_stats_kernel() {
    int c = threadIdx.x;
    if (c < OUT_C) {
        float mean = g_sum[c] * (1.0f / N_ATOMS);
        float var = g_sumsq[c] * (1.0f / N_ATOMS) - mean * mean;
        g_mean[c] = mean;
        g_istd[c] = rsqrtf(var + BN_EPS);
    }
}

__global__ void bn_relu_kernel(float4* __restrict__ x, int n4) {
    int t = blockIdx.x * blockDim.x + threadIdx.x;
    int stride = gridDim.x * blockDim.x;   // multiple of 32
    int c = (t & 31) * 4;
    float m0 = g_mean[c + 0], m1 = g_mean[c + 1], m2 = g_mean[c + 2], m3 = g_mean[c + 3];
    float i0 = g_istd[c + 0], i1 = g_istd[c + 1], i2 = g_istd[c + 2], i3 = g_istd[c + 3];
    for (int i = t; i < n4; i += stride) {
        float4 v = x[i];
        v.x = fmaxf((v.x - m0) * i0, 0.f);
        v.y = fmaxf((v.y - m1) * i1, 0.f);
        v.z = fmaxf((v.z - m2) * i2, 0.f);
        v.w = fmaxf((v.w - m3) * i3, 0.f);
        x[i] = v;
    }
}

// ---------------- launch ----------------
extern "C" void kernel_launch(void* const* d_in, const int* in_sizes, int n_in,
                              void* d_out, int out_size) {
    (void)n_in; (void)out_size;

    const float* atom_repr = (const float*)d_in[0];
    const float* bond_repr = (const float*)d_in[1];
    const int* aidx[4];
    const int* bidx[4];
    const float* W[4];

    if (in_sizes[4] == OUT_C * (NODE + EDGE)) {
        for (int d = 0; d < 4; d++) {
            aidx[d] = (const int*)d_in[2 + 3 * d];
            bidx[d] = (const int*)d_in[3 + 3 * d];
            W[d]    = (const float*)d_in[4 + 3 * d];
        }
    } else {
        for (int d = 0; d < 4; d++) {
            aidx[d] = (const int*)d_in[2 + d];
            bidx[d] = (const int*)d_in[6 + d];
            W[d]    = (const float*)d_in[10 + d];
        }
    }
    const float* Wself = (const float*)d_in[14];
    const float* bias  = (const float*)d_in[15];
    float* out = (float*)d_out;

    cudaFuncSetAttribute(gemm_kernel, cudaFuncAttributeMaxDynamicSharedMemorySize, P2_SMEM);

    zero_stats_kernel<<<1, 128>>>();
    wconv_kernel<<<(OUT_C * 192 + 255) / 256, 256>>>(W[0], W[1], W[2], W[3], Wself);
    gather_kernel<<<(N_ATOMS * 32) / 256, 256>>>(
        atom_repr, bond_repr,
        aidx[0], aidx[1], aidx[2], aidx[3],
        bidx[0], bidx[1], bidx[2], bidx[3]);
    gemm_kernel<<<4 * N_TILES, 256, P2_SMEM>>>(atom_repr, bias, out);
    finalize_stats_kernel<<<1, 128>>>();
    const int n4 = (N_ATOMS * OUT_C) / 4;
    bn_relu_kernel<<<2960, 256>>>((float4*)out, n4);
}